// round 9
// baseline (speedup 1.0000x reference)
#include <cuda_runtime.h>
#include <cstdint>

// ---------------------------------------------------------------------------
// out[i] = sum_{e: w_rows[e]==i} Param_W[w_params[e]] * x[w_cols[e]]
//          + Param_b[b_params[i]]
//
// N = 262144, E = 16.7M. Established by R1-R7 ablations: the edge kernel is
// L1tex-WAVEFRONT bound (~2 wavefronts/edge from divergent gathers + REDs),
// at 97% of that ceiling. Byte-level tricks (fp16 x, .cs, smem) are provably
// neutral-or-worse. R8: fp32 path + persistent grid-stride (1184 CTAs =
// 148 SMs x 8) to remove ~15K CTA launches / 14 wave transitions / end tail.
// ---------------------------------------------------------------------------

#define PERSISTENT_CTAS 1184   // 148 SMs x 8 CTAs (256 thr, 30 regs -> fits)

__global__ void bias_init_vec4_kernel(const float* __restrict__ Param_b,
                                      const int4*  __restrict__ b_params4,
                                      float4*      __restrict__ out4,
                                      int N4)
{
    int i = blockIdx.x * blockDim.x + threadIdx.x;
    if (i < N4) {
        int4 b = b_params4[i];
        float4 o;
        o.x = __ldg(&Param_b[b.x]);
        o.y = __ldg(&Param_b[b.y]);
        o.z = __ldg(&Param_b[b.z]);
        o.w = __ldg(&Param_b[b.w]);
        out4[i] = o;
    }
}

__global__ void bias_init_tail_kernel(const float* __restrict__ Param_b,
                                      const int*   __restrict__ b_params,
                                      float*       __restrict__ out,
                                      int start, int N)
{
    int i = start + blockIdx.x * blockDim.x + threadIdx.x;
    if (i < N) out[i] = __ldg(&Param_b[b_params[i]]);
}

// Persistent edge scatter: each thread strides over quads of edges.
// Body identical to the proven R1/R4 shape (fp32 gathers, __ldcs streams).
__global__ void __launch_bounds__(256)
edge_scatter_persistent_kernel(const float* __restrict__ x,
                               const float* __restrict__ Param_W,
                               const int4*  __restrict__ rows4,
                               const int4*  __restrict__ cols4,
                               const int4*  __restrict__ params4,
                               float*       __restrict__ out,
                               int E4)
{
    int stride = gridDim.x * blockDim.x;
    for (int t = blockIdx.x * blockDim.x + threadIdx.x; t < E4; t += stride) {
        int4 r = __ldcs(&rows4[t]);
        int4 c = __ldcs(&cols4[t]);
        int4 p = __ldcs(&params4[t]);

        float v0 = __ldg(&Param_W[p.x]) * __ldg(&x[c.x]);
        float v1 = __ldg(&Param_W[p.y]) * __ldg(&x[c.y]);
        float v2 = __ldg(&Param_W[p.z]) * __ldg(&x[c.z]);
        float v3 = __ldg(&Param_W[p.w]) * __ldg(&x[c.w]);

        atomicAdd(&out[r.x], v0);
        atomicAdd(&out[r.y], v1);
        atomicAdd(&out[r.z], v2);
        atomicAdd(&out[r.w], v3);
    }
}

__global__ void edge_scatter_tail_kernel(const float* __restrict__ x,
                                         const float* __restrict__ Param_W,
                                         const int*   __restrict__ rows,
                                         const int*   __restrict__ cols,
                                         const int*   __restrict__ params,
                                         float*       __restrict__ out,
                                         int start, int E)
{
    int e = start + blockIdx.x * blockDim.x + threadIdx.x;
    if (e < E) {
        float v = __ldg(&Param_W[params[e]]) * __ldg(&x[cols[e]]);
        atomicAdd(&out[rows[e]], v);
    }
}

extern "C" void kernel_launch(void* const* d_in, const int* in_sizes, int n_in,
                              void* d_out, int out_size)
{
    const float* x        = (const float*)d_in[0];
    const float* Param_W  = (const float*)d_in[1];
    const float* Param_b  = (const float*)d_in[2];
    const int*   w_rows   = (const int*)  d_in[3];
    const int*   w_cols   = (const int*)  d_in[4];
    const int*   w_params = (const int*)  d_in[5];
    const int*   b_params = (const int*)  d_in[6];
    float*       out      = (float*)d_out;

    const int N = out_size;       // 262144
    const int E = in_sizes[3];    // 16777216

    // 1) out = gathered bias (plain stores; clears poison; precedes atomics).
    {
        int N4 = N / 4;
        if (N4 > 0) {
            int threads = 256;
            int blocks  = (N4 + threads - 1) / threads;
            bias_init_vec4_kernel<<<blocks, threads>>>(
                Param_b, (const int4*)b_params, (float4*)out, N4);
        }
        int rem = N4 * 4;
        if (N - rem > 0) {
            bias_init_tail_kernel<<<1, 256>>>(Param_b, b_params, out, rem, N);
        }
    }

    // 2) Persistent edge scatter: single wave of 1184 CTAs, grid-stride.
    {
        int E4 = E / 4;
        if (E4 > 0) {
            int threads = 256;
            int work_blocks = (E4 + threads - 1) / threads;
            int blocks = work_blocks < PERSISTENT_CTAS ? work_blocks
                                                       : PERSISTENT_CTAS;
            edge_scatter_persistent_kernel<<<blocks, threads>>>(
                x, Param_W,
                (const int4*)w_rows, (const int4*)w_cols, (const int4*)w_params,
                out, E4);
        }
        int tail_start = E4 * 4;
        if (E - tail_start > 0) {
            edge_scatter_tail_kernel<<<1, 256>>>(
                x, Param_W, w_rows, w_cols, w_params, out, tail_start, E);
        }
    }
}

// round 10
// speedup vs baseline: 1.1808x; 1.1808x over previous
#include <cuda_runtime.h>
#include <cstdint>

// ---------------------------------------------------------------------------
// out[i] = sum_{e: w_rows[e]==i} Param_W[w_params[e]] * x[w_cols[e]]
//          + Param_b[b_params[i]]
//
// N = 262144, E = 16.7M. Edge kernel (16384x256, 4 edges/thread) sits at 97%
// of the L1tex-wavefront ceiling — established floor. R9 removes the last
// serialized overhead: edges accumulate into a __device__ scratch that is
// zero on entry (zeroed at load, re-zeroed by the epilogue each call), so
// NOTHING runs ahead of the edge kernel. Epilogue: out = scratch + bias,
// scratch = 0. Deterministic, graph-capturable, allocation-free.
// ---------------------------------------------------------------------------

#define NMAX 262144

__device__ float g_acc[NMAX];   // zero-initialized at module load

// --- main edge scatter: proven R1 shape, target = g_acc -------------------
__global__ void __launch_bounds__(256)
edge_scatter_vec4_kernel(const float* __restrict__ x,
                         const float* __restrict__ Param_W,
                         const int4*  __restrict__ rows4,
                         const int4*  __restrict__ cols4,
                         const int4*  __restrict__ params4,
                         int E4)
{
    int t = blockIdx.x * blockDim.x + threadIdx.x;
    if (t >= E4) return;

    int4 r = __ldcs(&rows4[t]);
    int4 c = __ldcs(&cols4[t]);
    int4 p = __ldcs(&params4[t]);

    float v0 = __ldg(&Param_W[p.x]) * __ldg(&x[c.x]);
    float v1 = __ldg(&Param_W[p.y]) * __ldg(&x[c.y]);
    float v2 = __ldg(&Param_W[p.z]) * __ldg(&x[c.z]);
    float v3 = __ldg(&Param_W[p.w]) * __ldg(&x[c.w]);

    atomicAdd(&g_acc[r.x], v0);
    atomicAdd(&g_acc[r.y], v1);
    atomicAdd(&g_acc[r.z], v2);
    atomicAdd(&g_acc[r.w], v3);
}

__global__ void edge_scatter_tail_kernel(const float* __restrict__ x,
                                         const float* __restrict__ Param_W,
                                         const int*   __restrict__ rows,
                                         const int*   __restrict__ cols,
                                         const int*   __restrict__ params,
                                         int start, int E)
{
    int e = start + blockIdx.x * blockDim.x + threadIdx.x;
    if (e < E) {
        float v = __ldg(&Param_W[params[e]]) * __ldg(&x[cols[e]]);
        atomicAdd(&g_acc[rows[e]], v);
    }
}

// --- epilogue: out = acc + bias; acc = 0 (restores invariant) -------------
__global__ void __launch_bounds__(256)
epilogue_vec4_kernel(const float* __restrict__ Param_b,
                     const int4*  __restrict__ b_params4,
                     float4*      __restrict__ out4,
                     int N4)
{
    int i = blockIdx.x * blockDim.x + threadIdx.x;
    if (i < N4) {
        float4* acc4 = (float4*)&g_acc[i * 4];
        float4 a = *acc4;
        int4   b = b_params4[i];
        float4 o;
        o.x = a.x + __ldg(&Param_b[b.x]);
        o.y = a.y + __ldg(&Param_b[b.y]);
        o.z = a.z + __ldg(&Param_b[b.z]);
        o.w = a.w + __ldg(&Param_b[b.w]);
        out4[i] = o;
        *acc4 = make_float4(0.f, 0.f, 0.f, 0.f);
    }
}

__global__ void epilogue_tail_kernel(const float* __restrict__ Param_b,
                                     const int*   __restrict__ b_params,
                                     float*       __restrict__ out,
                                     int start, int N)
{
    int i = start + blockIdx.x * blockDim.x + threadIdx.x;
    if (i < N) {
        out[i] = g_acc[i] + __ldg(&Param_b[b_params[i]]);
        g_acc[i] = 0.f;
    }
}

// --- fallback for N > NMAX: bias-first + direct atomics into out ----------
__global__ void bias_only_kernel(const float* __restrict__ Param_b,
                                 const int*   __restrict__ b_params,
                                 float*       __restrict__ out, int N)
{
    int i = blockIdx.x * blockDim.x + threadIdx.x;
    if (i < N) out[i] = __ldg(&Param_b[b_params[i]]);
}

__global__ void edge_scatter_direct_kernel(const float* __restrict__ x,
                                           const float* __restrict__ Param_W,
                                           const int*   __restrict__ rows,
                                           const int*   __restrict__ cols,
                                           const int*   __restrict__ params,
                                           float*       __restrict__ out,
                                           int E)
{
    int e = blockIdx.x * blockDim.x + threadIdx.x;
    if (e < E) {
        float v = __ldg(&Param_W[params[e]]) * __ldg(&x[cols[e]]);
        atomicAdd(&out[rows[e]], v);
    }
}

extern "C" void kernel_launch(void* const* d_in, const int* in_sizes, int n_in,
                              void* d_out, int out_size)
{
    const float* x        = (const float*)d_in[0];
    const float* Param_W  = (const float*)d_in[1];
    const float* Param_b  = (const float*)d_in[2];
    const int*   w_rows   = (const int*)  d_in[3];
    const int*   w_cols   = (const int*)  d_in[4];
    const int*   w_params = (const int*)  d_in[5];
    const int*   b_params = (const int*)  d_in[6];
    float*       out      = (float*)d_out;

    const int N = out_size;       // 262144
    const int E = in_sizes[3];    // 16777216

    if (N > NMAX) {
        // Fallback path for unexpected shapes.
        bias_only_kernel<<<(N + 255) / 256, 256>>>(Param_b, b_params, out, N);
        edge_scatter_direct_kernel<<<(E + 255) / 256, 256>>>(
            x, Param_W, w_rows, w_cols, w_params, out, E);
        return;
    }

    // 1) Edge scatter into g_acc (zero on entry) — starts immediately.
    int E4 = E / 4;
    if (E4 > 0) {
        int threads = 256;
        int blocks  = (E4 + threads - 1) / threads;
        edge_scatter_vec4_kernel<<<blocks, threads>>>(
            x, Param_W,
            (const int4*)w_rows, (const int4*)w_cols, (const int4*)w_params,
            E4);
    }
    int e_tail = E4 * 4;
    if (E - e_tail > 0) {
        edge_scatter_tail_kernel<<<1, 256>>>(
            x, Param_W, w_rows, w_cols, w_params, e_tail, E);
    }

    // 2) Epilogue: out = acc + gathered bias; acc reset to zero.
    int N4 = N / 4;
    if (N4 > 0) {
        int threads = 256;
        int blocks  = (N4 + threads - 1) / threads;
        epilogue_vec4_kernel<<<blocks, threads>>>(
            Param_b, (const int4*)b_params, (float4*)out, N4);
    }
    int n_tail = N4 * 4;
    if (N - n_tail > 0) {
        epilogue_tail_kernel<<<1, 256>>>(Param_b, b_params, out, n_tail, N);
    }
}